// round 2
// baseline (speedup 1.0000x reference)
#include <cuda_runtime.h>
#include <stdint.h>

#define BATCH   4096
#define IN_DIM  16384
#define OUT_DIM 16384
#define ROWS_PER_CTA 3
#define MAIN_THREADS 512

// Precomputed per-output-column data (row-invariant):
//   g_k[j]   = (k0,k1,k2,k3) = softmax(weights[j]) @ GATE_COEFFS
//   g_idx[j] = (a_idx[j], b_idx[j]) as int32
__device__ float4 g_k[OUT_DIM];
__device__ int2   g_idx[OUT_DIM];

__constant__ float c_gate[16][4] = {
    {0.f, 0.f, 0.f, 0.f}, {0.f, 0.f, 0.f, 1.f}, {0.f, 1.f, 0.f,-1.f}, {0.f, 1.f, 0.f, 0.f},
    {0.f, 0.f, 1.f,-1.f}, {0.f, 0.f, 1.f, 0.f}, {0.f, 1.f, 1.f,-2.f}, {0.f, 1.f, 1.f,-1.f},
    {1.f,-1.f,-1.f, 1.f}, {1.f,-1.f,-1.f, 2.f}, {1.f, 0.f,-1.f, 0.f}, {1.f, 0.f,-1.f, 1.f},
    {1.f,-1.f, 0.f, 0.f}, {1.f,-1.f, 0.f, 1.f}, {1.f, 0.f, 0.f,-1.f}, {1.f, 0.f, 0.f, 0.f}
};

// Detect whether an index buffer is int64 or int32 by inspecting the first
// 64 32-bit words: for an int64 buffer of values in [0, IN_DIM), every odd
// word (high half) is 0. For int32 data that is astronomically unlikely.
__device__ __forceinline__ bool idx_is_int64(const int* p) {
    bool odd_all_zero = true;
    #pragma unroll
    for (int i = 1; i < 64; i += 2)
        odd_all_zero &= (p[i] == 0);
    return odd_all_zero;
}

__device__ __forceinline__ int load_index(const void* base, int j, bool is64) {
    if (is64) return (int)((const long long*)base)[j];
    return ((const int*)base)[j];
}

__global__ void prep_kernel(const float* __restrict__ w,
                            const void* __restrict__ a_idx,
                            const void* __restrict__ b_idx)
{
    int j = blockIdx.x * blockDim.x + threadIdx.x;
    if (j >= OUT_DIM) return;

    const bool a64 = idx_is_int64((const int*)a_idx);
    const bool b64 = idx_is_int64((const int*)b_idx);

    float wv[16];
    const float4* w4 = reinterpret_cast<const float4*>(w + (size_t)j * 16);
    #pragma unroll
    for (int q = 0; q < 4; q++) {
        float4 v = __ldg(&w4[q]);
        wv[q*4+0] = v.x; wv[q*4+1] = v.y; wv[q*4+2] = v.z; wv[q*4+3] = v.w;
    }
    float m = wv[0];
    #pragma unroll
    for (int i = 1; i < 16; i++) m = fmaxf(m, wv[i]);
    float e[16], s = 0.f;
    #pragma unroll
    for (int i = 0; i < 16; i++) { e[i] = __expf(wv[i] - m); s += e[i]; }
    float inv = 1.0f / s;

    float k0 = 0.f, k1 = 0.f, k2 = 0.f, k3 = 0.f;
    #pragma unroll
    for (int i = 0; i < 16; i++) {
        float p = e[i] * inv;
        k0 = fmaf(p, c_gate[i][0], k0);
        k1 = fmaf(p, c_gate[i][1], k1);
        k2 = fmaf(p, c_gate[i][2], k2);
        k3 = fmaf(p, c_gate[i][3], k3);
    }
    g_k[j]   = make_float4(k0, k1, k2, k3);
    g_idx[j] = make_int2(load_index(a_idx, j, a64), load_index(b_idx, j, b64));
}

// One CTA owns ROWS_PER_CTA batch rows. Full rows staged into smem (3 x 64KB),
// gathers become LDS, per-j metadata (k + idx) amortized over 3 rows.
__global__ void __launch_bounds__(MAIN_THREADS, 1)
logic_main_kernel(const float* __restrict__ x, float* __restrict__ out)
{
    extern __shared__ float s[];   // [nr][IN_DIM]
    const int row0 = blockIdx.x * ROWS_PER_CTA;
    const int nr   = min(ROWS_PER_CTA, BATCH - row0);
    const int tid  = threadIdx.x;

    // Stage nr contiguous rows (rows are contiguous in x) via float4.
    {
        const float4* __restrict__ src = reinterpret_cast<const float4*>(x + (size_t)row0 * IN_DIM);
        float4* __restrict__ dst = reinterpret_cast<float4*>(s);
        const int n4 = nr * (IN_DIM / 4);
        for (int i = tid; i < n4; i += MAIN_THREADS)
            dst[i] = __ldg(&src[i]);
    }
    __syncthreads();

    float* __restrict__ o0 = out + (size_t)row0 * OUT_DIM;

    if (nr == ROWS_PER_CTA) {
        // fast path, fully unrolled over rows
        for (int j = tid; j < OUT_DIM; j += MAIN_THREADS) {
            float4 k = __ldg(&g_k[j]);
            int2  ij = __ldg(&g_idx[j]);
            #pragma unroll
            for (int r = 0; r < ROWS_PER_CTA; r++) {
                float a = s[r * IN_DIM + ij.x];
                float b = s[r * IN_DIM + ij.y];
                // k0 + k1*a + k2*b + k3*a*b  ==  k0 + k2*b + a*(k1 + k3*b)
                float v = fmaf(a, fmaf(k.w, b, k.y), fmaf(k.z, b, k.x));
                o0[(size_t)r * OUT_DIM + j] = v;
            }
        }
    } else {
        for (int j = tid; j < OUT_DIM; j += MAIN_THREADS) {
            float4 k = __ldg(&g_k[j]);
            int2  ij = __ldg(&g_idx[j]);
            for (int r = 0; r < nr; r++) {
                float a = s[r * IN_DIM + ij.x];
                float b = s[r * IN_DIM + ij.y];
                float v = fmaf(a, fmaf(k.w, b, k.y), fmaf(k.z, b, k.x));
                o0[(size_t)r * OUT_DIM + j] = v;
            }
        }
    }
}

extern "C" void kernel_launch(void* const* d_in, const int* in_sizes, int n_in,
                              void* d_out, int out_size)
{
    const float* x  = (const float*)d_in[0];
    const float* w  = (const float*)d_in[1];
    const void*  ai = d_in[2];
    const void*  bi = d_in[3];
    float* out = (float*)d_out;

    (void)in_sizes; (void)n_in; (void)out_size;

    const int smem_bytes = ROWS_PER_CTA * IN_DIM * sizeof(float); // 196608
    cudaFuncSetAttribute(logic_main_kernel,
                         cudaFuncAttributeMaxDynamicSharedMemorySize, smem_bytes);

    prep_kernel<<<(OUT_DIM + 255) / 256, 256>>>(w, ai, bi);

    const int grid = (BATCH + ROWS_PER_CTA - 1) / ROWS_PER_CTA; // 1366
    logic_main_kernel<<<grid, MAIN_THREADS, smem_bytes>>>(x, out);
}

// round 3
// speedup vs baseline: 1.0928x; 1.0928x over previous
#include <cuda_runtime.h>
#include <cuda_fp16.h>
#include <stdint.h>

#define BATCH   4096
#define IN_DIM  16384
#define OUT_DIM 16384
#define THREADS 1024
#define ROW_BYTES (IN_DIM * 4)          // 65536
#define NSLOT 3

// Packed per-output-column record (16B, one LDG.128):
//  w0 = fp32 k0
//  w1 = half2(k1, k2)
//  w2 = half k3 (low 16) | a_idx << 16
//  w3 = b_idx
struct __align__(16) Rec { unsigned int w0, w1, w2, w3; };
__device__ Rec g_rec[OUT_DIM];

__constant__ float c_gate[16][4] = {
    {0.f, 0.f, 0.f, 0.f}, {0.f, 0.f, 0.f, 1.f}, {0.f, 1.f, 0.f,-1.f}, {0.f, 1.f, 0.f, 0.f},
    {0.f, 0.f, 1.f,-1.f}, {0.f, 0.f, 1.f, 0.f}, {0.f, 1.f, 1.f,-2.f}, {0.f, 1.f, 1.f,-1.f},
    {1.f,-1.f,-1.f, 1.f}, {1.f,-1.f,-1.f, 2.f}, {1.f, 0.f,-1.f, 0.f}, {1.f, 0.f,-1.f, 1.f},
    {1.f,-1.f, 0.f, 0.f}, {1.f,-1.f, 0.f, 1.f}, {1.f, 0.f, 0.f,-1.f}, {1.f, 0.f, 0.f, 0.f}
};

// int64-vs-int32 buffer detection (R1 fix): for int64 indices in [0, IN_DIM),
// every odd 32-bit word is zero; astronomically unlikely for int32 data.
__device__ __forceinline__ bool idx_is_int64(const int* p) {
    bool odd_all_zero = true;
    #pragma unroll
    for (int i = 1; i < 64; i += 2) odd_all_zero &= (p[i] == 0);
    return odd_all_zero;
}
__device__ __forceinline__ int load_index(const void* base, int j, bool is64) {
    if (is64) return (int)((const long long*)base)[j];
    return ((const int*)base)[j];
}

__global__ void prep_kernel(const float* __restrict__ w,
                            const void* __restrict__ a_idx,
                            const void* __restrict__ b_idx)
{
    int j = blockIdx.x * blockDim.x + threadIdx.x;
    if (j >= OUT_DIM) return;

    const bool a64 = idx_is_int64((const int*)a_idx);
    const bool b64 = idx_is_int64((const int*)b_idx);

    float wv[16];
    const float4* w4 = reinterpret_cast<const float4*>(w + (size_t)j * 16);
    #pragma unroll
    for (int q = 0; q < 4; q++) {
        float4 v = __ldg(&w4[q]);
        wv[q*4+0] = v.x; wv[q*4+1] = v.y; wv[q*4+2] = v.z; wv[q*4+3] = v.w;
    }
    float m = wv[0];
    #pragma unroll
    for (int i = 1; i < 16; i++) m = fmaxf(m, wv[i]);
    float e[16], s = 0.f;
    #pragma unroll
    for (int i = 0; i < 16; i++) { e[i] = __expf(wv[i] - m); s += e[i]; }
    float inv = 1.0f / s;

    float k0 = 0.f, k1 = 0.f, k2 = 0.f, k3 = 0.f;
    #pragma unroll
    for (int i = 0; i < 16; i++) {
        float p = e[i] * inv;
        k0 = fmaf(p, c_gate[i][0], k0);
        k1 = fmaf(p, c_gate[i][1], k1);
        k2 = fmaf(p, c_gate[i][2], k2);
        k3 = fmaf(p, c_gate[i][3], k3);
    }

    unsigned int ia = (unsigned int)load_index(a_idx, j, a64);
    unsigned int ib = (unsigned int)load_index(b_idx, j, b64);

    Rec r;
    r.w0 = __float_as_uint(k0);
    __half2 h12 = __floats2half2_rn(k1, k2);
    r.w1 = *reinterpret_cast<unsigned int*>(&h12);
    __half h3 = __float2half_rn(k3);
    r.w2 = (unsigned int)*reinterpret_cast<unsigned short*>(&h3) | (ia << 16);
    r.w3 = ib;
    g_rec[j] = r;
}

// ---- mbarrier / TMA-bulk helpers ----
__device__ __forceinline__ uint32_t smem_u32(const void* p) {
    uint32_t a;
    asm("{ .reg .u64 t; cvta.to.shared.u64 t, %1; cvt.u32.u64 %0, t; }" : "=r"(a) : "l"(p));
    return a;
}
__device__ __forceinline__ void mbar_init(uint32_t mbar, uint32_t cnt) {
    asm volatile("mbarrier.init.shared.b64 [%0], %1;" :: "r"(mbar), "r"(cnt) : "memory");
}
__device__ __forceinline__ void mbar_expect_tx(uint32_t mbar, uint32_t bytes) {
    asm volatile("mbarrier.arrive.expect_tx.shared.b64 _, [%0], %1;"
                 :: "r"(mbar), "r"(bytes) : "memory");
}
__device__ __forceinline__ void mbar_wait(uint32_t mbar, uint32_t phase) {
    asm volatile(
        "{\n\t.reg .pred P;\n\t"
        "WL_%=:\n\t"
        "mbarrier.try_wait.parity.acquire.cta.shared::cta.b64 P, [%0], %1, 0x989680;\n\t"
        "@P bra.uni WD_%=;\n\t"
        "bra.uni WL_%=;\n\t"
        "WD_%=:\n\t}"
        :: "r"(mbar), "r"(phase) : "memory");
}
__device__ __forceinline__ void bulk_g2s(uint32_t dst, const void* src, uint32_t bytes, uint32_t mbar) {
    asm volatile(
        "cp.async.bulk.shared::cta.global.mbarrier::complete_tx::bytes [%0], [%1], %2, [%3];"
        :: "r"(dst), "l"(src), "r"(bytes), "r"(mbar) : "memory");
}

// Persistent kernel: grid = #SMs. Each CTA owns rows {c, c+nsm, ...}.
// smem = 3-slot x 64KB row ring; cp.async.bulk keeps 2 rows in flight while
// computing the current one -> staging fully overlapped with compute.
__global__ void __launch_bounds__(THREADS, 1)
logic_main_kernel(const float* __restrict__ x, float* __restrict__ out, int nsm)
{
    extern __shared__ unsigned char smem_raw[];
    float* slot_f[NSLOT];
    uint32_t slot_a[NSLOT], mbar[NSLOT];
    const uint32_t base = smem_u32(smem_raw);
    #pragma unroll
    for (int s = 0; s < NSLOT; s++) {
        slot_f[s] = reinterpret_cast<float*>(smem_raw + (size_t)s * ROW_BYTES);
        slot_a[s] = base + s * ROW_BYTES;
        mbar[s]   = base + NSLOT * ROW_BYTES + s * 8;
    }

    const int c   = blockIdx.x;
    const int tid = threadIdx.x;
    const int nrows = (BATCH - c + nsm - 1) / nsm;   // rows r = c + i*nsm

    if (tid == 0) {
        #pragma unroll
        for (int s = 0; s < NSLOT; s++) mbar_init(mbar[s], 1);
        asm volatile("fence.proxy.async.shared::cta;" ::: "memory");
    }
    __syncthreads();

    // Prologue: fill up to 3 slots.
    if (tid == 0) {
        int np = nrows < NSLOT ? nrows : NSLOT;
        for (int i = 0; i < np; i++) {
            mbar_expect_tx(mbar[i], ROW_BYTES);
            bulk_g2s(slot_a[i], x + (size_t)(c + i * nsm) * IN_DIM, ROW_BYTES, mbar[i]);
        }
    }

    for (int i = 0; i < nrows; i++) {
        const int s  = i % NSLOT;
        const uint32_t ph = (uint32_t)((i / NSLOT) & 1);
        mbar_wait(mbar[s], ph);

        const float* __restrict__ xs = slot_f[s];
        float* __restrict__ o = out + (size_t)(c + i * nsm) * OUT_DIM;

        #pragma unroll 4
        for (int j = tid; j < OUT_DIM; j += THREADS) {
            uint4 m = __ldg(reinterpret_cast<const uint4*>(&g_rec[j]));
            float k0 = __uint_as_float(m.x);
            __half2 h12 = *reinterpret_cast<__half2*>(&m.y);
            float2 k12 = __half22float2(h12);
            unsigned short h3u = (unsigned short)(m.z & 0xFFFFu);
            float k3 = __half2float(*reinterpret_cast<__half*>(&h3u));
            int ia = (int)(m.z >> 16);
            int ib = (int)(m.w & 0xFFFFu);

            float a = xs[ia];
            float b = xs[ib];
            // k0 + k1*a + k2*b + k3*a*b
            float v = fmaf(a, fmaf(k3, b, k12.x), fmaf(k12.y, b, k0));
            __stcs(&o[j], v);
        }

        __syncthreads();   // everyone done reading slot s before refill
        if (tid == 0 && i + NSLOT < nrows) {
            mbar_expect_tx(mbar[s], ROW_BYTES);
            bulk_g2s(slot_a[s], x + (size_t)(c + (i + NSLOT) * nsm) * IN_DIM,
                     ROW_BYTES, mbar[s]);
        }
    }
}

extern "C" void kernel_launch(void* const* d_in, const int* in_sizes, int n_in,
                              void* d_out, int out_size)
{
    const float* x  = (const float*)d_in[0];
    const float* w  = (const float*)d_in[1];
    const void*  ai = d_in[2];
    const void*  bi = d_in[3];
    float* out = (float*)d_out;
    (void)in_sizes; (void)n_in; (void)out_size;

    int nsm = 148;
    cudaDeviceGetAttribute(&nsm, cudaDevAttrMultiProcessorCount, 0);

    const int smem_bytes = NSLOT * ROW_BYTES + NSLOT * 8 + 64; // 3x64KB ring + mbarriers
    cudaFuncSetAttribute(logic_main_kernel,
                         cudaFuncAttributeMaxDynamicSharedMemorySize, smem_bytes);

    prep_kernel<<<(OUT_DIM + 255) / 256, 256>>>(w, ai, bi);
    logic_main_kernel<<<nsm, THREADS, smem_bytes>>>(x, out, nsm);
}

// round 4
// speedup vs baseline: 1.1765x; 1.0766x over previous
#include <cuda_runtime.h>
#include <cuda_fp16.h>
#include <stdint.h>

#define BATCH   4096
#define IN_DIM  16384
#define OUT_DIM 16384
#define THREADS 1024
#define PAIRS   (BATCH / 2)

// Packed per-output-column record (16B, one LDG.128):
//  w0 = fp32 k0 ; w1 = half2(k1,k2) ; w2 = half k3 | a_idx<<16 ; w3 = b_idx
struct __align__(16) Rec { unsigned int w0, w1, w2, w3; };
__device__ Rec g_rec[OUT_DIM];

__constant__ float c_gate[16][4] = {
    {0.f, 0.f, 0.f, 0.f}, {0.f, 0.f, 0.f, 1.f}, {0.f, 1.f, 0.f,-1.f}, {0.f, 1.f, 0.f, 0.f},
    {0.f, 0.f, 1.f,-1.f}, {0.f, 0.f, 1.f, 0.f}, {0.f, 1.f, 1.f,-2.f}, {0.f, 1.f, 1.f,-1.f},
    {1.f,-1.f,-1.f, 1.f}, {1.f,-1.f,-1.f, 2.f}, {1.f, 0.f,-1.f, 0.f}, {1.f, 0.f,-1.f, 1.f},
    {1.f,-1.f, 0.f, 0.f}, {1.f,-1.f, 0.f, 1.f}, {1.f, 0.f, 0.f,-1.f}, {1.f, 0.f, 0.f, 0.f}
};

// int64-vs-int32 buffer detection (R1 fix).
__device__ __forceinline__ bool idx_is_int64(const int* p) {
    bool odd_all_zero = true;
    #pragma unroll
    for (int i = 1; i < 64; i += 2) odd_all_zero &= (p[i] == 0);
    return odd_all_zero;
}
__device__ __forceinline__ int load_index(const void* base, int j, bool is64) {
    if (is64) return (int)((const long long*)base)[j];
    return ((const int*)base)[j];
}

__global__ void prep_kernel(const float* __restrict__ w,
                            const void* __restrict__ a_idx,
                            const void* __restrict__ b_idx)
{
    int j = blockIdx.x * blockDim.x + threadIdx.x;
    if (j >= OUT_DIM) return;

    const bool a64 = idx_is_int64((const int*)a_idx);
    const bool b64 = idx_is_int64((const int*)b_idx);

    float wv[16];
    const float4* w4 = reinterpret_cast<const float4*>(w + (size_t)j * 16);
    #pragma unroll
    for (int q = 0; q < 4; q++) {
        float4 v = __ldg(&w4[q]);
        wv[q*4+0] = v.x; wv[q*4+1] = v.y; wv[q*4+2] = v.z; wv[q*4+3] = v.w;
    }
    float m = wv[0];
    #pragma unroll
    for (int i = 1; i < 16; i++) m = fmaxf(m, wv[i]);
    float e[16], s = 0.f;
    #pragma unroll
    for (int i = 0; i < 16; i++) { e[i] = __expf(wv[i] - m); s += e[i]; }
    float inv = 1.0f / s;

    float k0 = 0.f, k1 = 0.f, k2 = 0.f, k3 = 0.f;
    #pragma unroll
    for (int i = 0; i < 16; i++) {
        float p = e[i] * inv;
        k0 = fmaf(p, c_gate[i][0], k0);
        k1 = fmaf(p, c_gate[i][1], k1);
        k2 = fmaf(p, c_gate[i][2], k2);
        k3 = fmaf(p, c_gate[i][3], k3);
    }

    unsigned int ia = (unsigned int)load_index(a_idx, j, a64);
    unsigned int ib = (unsigned int)load_index(b_idx, j, b64);

    Rec r;
    r.w0 = __float_as_uint(k0);
    __half2 h12 = __floats2half2_rn(k1, k2);
    r.w1 = *reinterpret_cast<unsigned int*>(&h12);
    __half h3 = __float2half_rn(k3);
    r.w2 = (unsigned int)*reinterpret_cast<unsigned short*>(&h3) | (ia << 16);
    r.w3 = ib;
    g_rec[j] = r;
}

// Stage a row pair into smem as interleaved half2: dst[k] = {half(r0[k]), half(r1[k])}.
// 16384 cols / 4-per-iter / 1024 threads = 4 iterations; LDG.128 fp32 x2 -> STS.128.
__device__ __forceinline__ void stage_pair(const float* __restrict__ r0,
                                           const float* __restrict__ r1,
                                           __half2* __restrict__ dst, int tid)
{
    #pragma unroll
    for (int it = 0; it < 4; it++) {
        int k = (tid + it * THREADS) * 4;
        float4 e = __ldcs(reinterpret_cast<const float4*>(r0 + k));
        float4 o = __ldcs(reinterpret_cast<const float4*>(r1 + k));
        __half2 h0 = __floats2half2_rn(e.x, o.x);
        __half2 h1 = __floats2half2_rn(e.y, o.y);
        __half2 h2 = __floats2half2_rn(e.z, o.z);
        __half2 h3 = __floats2half2_rn(e.w, o.w);
        uint4 pk;
        pk.x = *reinterpret_cast<unsigned int*>(&h0);
        pk.y = *reinterpret_cast<unsigned int*>(&h1);
        pk.z = *reinterpret_cast<unsigned int*>(&h2);
        pk.w = *reinterpret_cast<unsigned int*>(&h3);
        *reinterpret_cast<uint4*>(dst + k) = pk;
    }
}

// Persistent kernel: CTA c owns pairs {c, c+nsm, ...}. Two 64KB half2 slots,
// software double-buffer: stage pair t+1 into slot s^1, compute pair t from
// slot s, one __syncthreads per iteration.
__global__ void __launch_bounds__(THREADS, 1)
logic_main_kernel(const float* __restrict__ x, float* __restrict__ out, int nsm)
{
    extern __shared__ __align__(16) unsigned char smem_raw[];
    __half2* slot[2] = {
        reinterpret_cast<__half2*>(smem_raw),
        reinterpret_cast<__half2*>(smem_raw + IN_DIM * sizeof(__half2))
    };
    const int c   = blockIdx.x;
    const int tid = threadIdx.x;

    if (c >= PAIRS) return;

    // Prologue: stage first pair into slot 0.
    stage_pair(x + (size_t)(2 * c) * IN_DIM,
               x + (size_t)(2 * c + 1) * IN_DIM, slot[0], tid);
    __syncthreads();

    int s = 0;
    for (int p = c; p < PAIRS; p += nsm, s ^= 1) {
        // Stage next pair into the other slot (overwrites pair computed 1 iter ago).
        const int pn = p + nsm;
        if (pn < PAIRS)
            stage_pair(x + (size_t)(2 * pn) * IN_DIM,
                       x + (size_t)(2 * pn + 1) * IN_DIM, slot[s ^ 1], tid);

        const __half2* __restrict__ xs = slot[s];
        float* __restrict__ oe = out + (size_t)(2 * p) * OUT_DIM;
        float* __restrict__ oo = oe + OUT_DIM;

        #pragma unroll 4
        for (int j = tid; j < OUT_DIM; j += THREADS) {
            uint4 m = __ldg(reinterpret_cast<const uint4*>(&g_rec[j]));
            float  k0  = __uint_as_float(m.x);
            float2 k12 = __half22float2(*reinterpret_cast<__half2*>(&m.y));
            unsigned short h3u = (unsigned short)(m.z & 0xFFFFu);
            float  k3  = __half2float(*reinterpret_cast<__half*>(&h3u));
            int ia = (int)(m.z >> 16);
            int ib = (int)m.w;

            float2 a = __half22float2(xs[ia]);   // {row even, row odd}
            float2 b = __half22float2(xs[ib]);

            float ve = fmaf(a.x, fmaf(k3, b.x, k12.x), fmaf(k12.y, b.x, k0));
            float vo = fmaf(a.y, fmaf(k3, b.y, k12.x), fmaf(k12.y, b.y, k0));
            __stcs(&oe[j], ve);
            __stcs(&oo[j], vo);
        }
        __syncthreads();
    }
}

extern "C" void kernel_launch(void* const* d_in, const int* in_sizes, int n_in,
                              void* d_out, int out_size)
{
    const float* x  = (const float*)d_in[0];
    const float* w  = (const float*)d_in[1];
    const void*  ai = d_in[2];
    const void*  bi = d_in[3];
    float* out = (float*)d_out;
    (void)in_sizes; (void)n_in; (void)out_size;

    int nsm = 148;
    cudaDeviceGetAttribute(&nsm, cudaDevAttrMultiProcessorCount, 0);

    const int smem_bytes = 2 * IN_DIM * sizeof(__half2); // 2 x 64KB
    cudaFuncSetAttribute(logic_main_kernel,
                         cudaFuncAttributeMaxDynamicSharedMemorySize, smem_bytes);

    prep_kernel<<<(OUT_DIM + 255) / 256, 256>>>(w, ai, bi);
    logic_main_kernel<<<nsm, THREADS, smem_bytes>>>(x, out, nsm);
}

// round 5
// speedup vs baseline: 1.2155x; 1.0332x over previous
#include <cuda_runtime.h>
#include <cuda_fp16.h>
#include <stdint.h>

#define BATCH   4096
#define IN_DIM  16384
#define OUT_DIM 16384
#define THREADS 1024
#define PAIRS   (BATCH / 2)
#define JPT     (OUT_DIM / THREADS)       // 16 j per thread
#define NGROUP  (JPT / 4)                 // 4 groups of 4 consecutive j

// Per-j k coefficients, 8B: x = half2(k0,k1), y = half2(k2,k3)
__device__ uint2    g_k8[OUT_DIM];
// Per-j packed indices: a | (b<<16)
__device__ uint32_t g_idx_pack[OUT_DIM];

__constant__ float c_gate[16][4] = {
    {0.f, 0.f, 0.f, 0.f}, {0.f, 0.f, 0.f, 1.f}, {0.f, 1.f, 0.f,-1.f}, {0.f, 1.f, 0.f, 0.f},
    {0.f, 0.f, 1.f,-1.f}, {0.f, 0.f, 1.f, 0.f}, {0.f, 1.f, 1.f,-2.f}, {0.f, 1.f, 1.f,-1.f},
    {1.f,-1.f,-1.f, 1.f}, {1.f,-1.f,-1.f, 2.f}, {1.f, 0.f,-1.f, 0.f}, {1.f, 0.f,-1.f, 1.f},
    {1.f,-1.f, 0.f, 0.f}, {1.f,-1.f, 0.f, 1.f}, {1.f, 0.f, 0.f,-1.f}, {1.f, 0.f, 0.f, 0.f}
};

// int64-vs-int32 buffer detection (R1 fix).
__device__ __forceinline__ bool idx_is_int64(const int* p) {
    bool odd_all_zero = true;
    #pragma unroll
    for (int i = 1; i < 64; i += 2) odd_all_zero &= (p[i] == 0);
    return odd_all_zero;
}
__device__ __forceinline__ int load_index(const void* base, int j, bool is64) {
    if (is64) return (int)((const long long*)base)[j];
    return ((const int*)base)[j];
}

__global__ void prep_kernel(const float* __restrict__ w,
                            const void* __restrict__ a_idx,
                            const void* __restrict__ b_idx)
{
    int j = blockIdx.x * blockDim.x + threadIdx.x;
    if (j >= OUT_DIM) return;

    const bool a64 = idx_is_int64((const int*)a_idx);
    const bool b64 = idx_is_int64((const int*)b_idx);

    float wv[16];
    const float4* w4 = reinterpret_cast<const float4*>(w + (size_t)j * 16);
    #pragma unroll
    for (int q = 0; q < 4; q++) {
        float4 v = __ldg(&w4[q]);
        wv[q*4+0] = v.x; wv[q*4+1] = v.y; wv[q*4+2] = v.z; wv[q*4+3] = v.w;
    }
    float m = wv[0];
    #pragma unroll
    for (int i = 1; i < 16; i++) m = fmaxf(m, wv[i]);
    float e[16], s = 0.f;
    #pragma unroll
    for (int i = 0; i < 16; i++) { e[i] = __expf(wv[i] - m); s += e[i]; }
    float inv = 1.0f / s;

    float k0 = 0.f, k1 = 0.f, k2 = 0.f, k3 = 0.f;
    #pragma unroll
    for (int i = 0; i < 16; i++) {
        float p = e[i] * inv;
        k0 = fmaf(p, c_gate[i][0], k0);
        k1 = fmaf(p, c_gate[i][1], k1);
        k2 = fmaf(p, c_gate[i][2], k2);
        k3 = fmaf(p, c_gate[i][3], k3);
    }

    unsigned int ia = (unsigned int)load_index(a_idx, j, a64);
    unsigned int ib = (unsigned int)load_index(b_idx, j, b64);

    __half2 h01 = __floats2half2_rn(k0, k1);
    __half2 h23 = __floats2half2_rn(k2, k3);
    uint2 k8;
    k8.x = *reinterpret_cast<unsigned int*>(&h01);
    k8.y = *reinterpret_cast<unsigned int*>(&h23);
    g_k8[j] = k8;
    g_idx_pack[j] = ia | (ib << 16);
}

// Stage a row pair into smem as interleaved half2: dst[k] = {half(r0[k]), half(r1[k])}.
__device__ __forceinline__ void stage_pair(const float* __restrict__ r0,
                                           const float* __restrict__ r1,
                                           __half2* __restrict__ dst, int tid)
{
    #pragma unroll
    for (int it = 0; it < 4; it++) {
        int k = (tid + it * THREADS) * 4;
        float4 e = __ldcs(reinterpret_cast<const float4*>(r0 + k));
        float4 o = __ldcs(reinterpret_cast<const float4*>(r1 + k));
        __half2 h0 = __floats2half2_rn(e.x, o.x);
        __half2 h1 = __floats2half2_rn(e.y, o.y);
        __half2 h2 = __floats2half2_rn(e.z, o.z);
        __half2 h3 = __floats2half2_rn(e.w, o.w);
        uint4 pk;
        pk.x = *reinterpret_cast<unsigned int*>(&h0);
        pk.y = *reinterpret_cast<unsigned int*>(&h1);
        pk.z = *reinterpret_cast<unsigned int*>(&h2);
        pk.w = *reinterpret_cast<unsigned int*>(&h3);
        *reinterpret_cast<uint4*>(dst + k) = pk;
    }
}

// Evaluate one j for both rows of the pair.
__device__ __forceinline__ void eval2(uint32_t idxp, uint32_t k01u, uint32_t k23u,
                                      const __half2* __restrict__ xs,
                                      float& ve, float& vo)
{
    float2 k01 = __half22float2(*reinterpret_cast<__half2*>(&k01u));  // k0,k1
    float2 k23 = __half22float2(*reinterpret_cast<__half2*>(&k23u));  // k2,k3
    float2 a = __half22float2(xs[idxp & 0xFFFFu]);
    float2 b = __half22float2(xs[idxp >> 16]);
    ve = fmaf(a.x, fmaf(k23.y, b.x, k01.y), fmaf(k23.x, b.x, k01.x));
    vo = fmaf(a.y, fmaf(k23.y, b.y, k01.y), fmaf(k23.x, b.y, k01.x));
}

// Persistent kernel. smem: 2 x 64KB half2 row-pair slots + 64KB packed indices.
__global__ void __launch_bounds__(THREADS, 1)
logic_main_kernel(const float* __restrict__ x, float* __restrict__ out, int nsm)
{
    extern __shared__ __align__(16) unsigned char smem_raw[];
    __half2* slot[2] = {
        reinterpret_cast<__half2*>(smem_raw),
        reinterpret_cast<__half2*>(smem_raw + IN_DIM * sizeof(__half2))
    };
    uint32_t* s_idx = reinterpret_cast<uint32_t*>(smem_raw + 2 * IN_DIM * sizeof(__half2));

    const int c   = blockIdx.x;
    const int tid = threadIdx.x;

    // Load packed indices into smem once (64KB, coalesced uint4).
    {
        const uint4* __restrict__ src = reinterpret_cast<const uint4*>(g_idx_pack);
        uint4* __restrict__ dst = reinterpret_cast<uint4*>(s_idx);
        #pragma unroll
        for (int i = 0; i < (OUT_DIM / 4) / THREADS; i++)
            dst[tid + i * THREADS] = __ldg(&src[tid + i * THREADS]);
    }
    // Prologue: stage first pair into slot 0.
    stage_pair(x + (size_t)(2 * c) * IN_DIM,
               x + (size_t)(2 * c + 1) * IN_DIM, slot[0], tid);
    __syncthreads();

    int s = 0;
    for (int p = c; p < PAIRS; p += nsm, s ^= 1) {
        const int pn = p + nsm;
        if (pn < PAIRS)
            stage_pair(x + (size_t)(2 * pn) * IN_DIM,
                       x + (size_t)(2 * pn + 1) * IN_DIM, slot[s ^ 1], tid);

        const __half2* __restrict__ xs = slot[s];
        float* __restrict__ oe = out + (size_t)(2 * p) * OUT_DIM;
        float* __restrict__ oo = oe + OUT_DIM;

        #pragma unroll
        for (int g = 0; g < NGROUP; g++) {
            const int j0 = g * (OUT_DIM / NGROUP) + tid * 4;
            // 4 consecutive j: indices via one LDS.128, k via two LDG.128.
            uint4 I   = *reinterpret_cast<const uint4*>(&s_idx[j0]);
            uint4 K01 = __ldg(reinterpret_cast<const uint4*>(&g_k8[j0]));     // j0, j0+1
            uint4 K23 = __ldg(reinterpret_cast<const uint4*>(&g_k8[j0 + 2])); // j0+2, j0+3

            float4 ve, vo;
            eval2(I.x, K01.x, K01.y, xs, ve.x, vo.x);
            eval2(I.y, K01.z, K01.w, xs, ve.y, vo.y);
            eval2(I.z, K23.x, K23.y, xs, ve.z, vo.z);
            eval2(I.w, K23.z, K23.w, xs, ve.w, vo.w);

            __stcs(reinterpret_cast<float4*>(&oe[j0]), ve);
            __stcs(reinterpret_cast<float4*>(&oo[j0]), vo);
        }
        __syncthreads();
    }
}

extern "C" void kernel_launch(void* const* d_in, const int* in_sizes, int n_in,
                              void* d_out, int out_size)
{
    const float* x  = (const float*)d_in[0];
    const float* w  = (const float*)d_in[1];
    const void*  ai = d_in[2];
    const void*  bi = d_in[3];
    float* out = (float*)d_out;
    (void)in_sizes; (void)n_in; (void)out_size;

    int nsm = 148;
    cudaDeviceGetAttribute(&nsm, cudaDevAttrMultiProcessorCount, 0);

    const int smem_bytes = 2 * IN_DIM * sizeof(__half2) + OUT_DIM * sizeof(uint32_t); // 192KB
    cudaFuncSetAttribute(logic_main_kernel,
                         cudaFuncAttributeMaxDynamicSharedMemorySize, smem_bytes);

    prep_kernel<<<(OUT_DIM + 255) / 256, 256>>>(w, ai, bi);
    logic_main_kernel<<<nsm, THREADS, smem_bytes>>>(x, out, nsm);
}

// round 6
// speedup vs baseline: 1.3701x; 1.1272x over previous
#include <cuda_runtime.h>
#include <cuda_fp16.h>
#include <stdint.h>

#define BATCH   4096
#define IN_DIM  16384
#define OUT_DIM 16384
#define THREADS 1024
#define QUADS   (BATCH / 4)               // 1024
#define JPT     (OUT_DIM / THREADS)       // 16 j per thread
#define NGROUP  (JPT / 4)                 // 4 groups of 4 consecutive j

// Per-j k coefficients, 8B: x = half2(k0,k1), y = half2(k2,k3)
__device__ uint2    g_k8[OUT_DIM];
// Per-j packed indices: a | (b<<16)
__device__ uint32_t g_idx_pack[OUT_DIM];

__constant__ float c_gate[16][4] = {
    {0.f, 0.f, 0.f, 0.f}, {0.f, 0.f, 0.f, 1.f}, {0.f, 1.f, 0.f,-1.f}, {0.f, 1.f, 0.f, 0.f},
    {0.f, 0.f, 1.f,-1.f}, {0.f, 0.f, 1.f, 0.f}, {0.f, 1.f, 1.f,-2.f}, {0.f, 1.f, 1.f,-1.f},
    {1.f,-1.f,-1.f, 1.f}, {1.f,-1.f,-1.f, 2.f}, {1.f, 0.f,-1.f, 0.f}, {1.f, 0.f,-1.f, 1.f},
    {1.f,-1.f, 0.f, 0.f}, {1.f,-1.f, 0.f, 1.f}, {1.f, 0.f, 0.f,-1.f}, {1.f, 0.f, 0.f, 0.f}
};

// int64-vs-int32 buffer detection (R1 fix).
__device__ __forceinline__ bool idx_is_int64(const int* p) {
    bool odd_all_zero = true;
    #pragma unroll
    for (int i = 1; i < 64; i += 2) odd_all_zero &= (p[i] == 0);
    return odd_all_zero;
}
__device__ __forceinline__ int load_index(const void* base, int j, bool is64) {
    if (is64) return (int)((const long long*)base)[j];
    return ((const int*)base)[j];
}

__global__ void prep_kernel(const float* __restrict__ w,
                            const void* __restrict__ a_idx,
                            const void* __restrict__ b_idx)
{
    int j = blockIdx.x * blockDim.x + threadIdx.x;
    if (j >= OUT_DIM) return;

    const bool a64 = idx_is_int64((const int*)a_idx);
    const bool b64 = idx_is_int64((const int*)b_idx);

    float wv[16];
    const float4* w4 = reinterpret_cast<const float4*>(w + (size_t)j * 16);
    #pragma unroll
    for (int q = 0; q < 4; q++) {
        float4 v = __ldg(&w4[q]);
        wv[q*4+0] = v.x; wv[q*4+1] = v.y; wv[q*4+2] = v.z; wv[q*4+3] = v.w;
    }
    float m = wv[0];
    #pragma unroll
    for (int i = 1; i < 16; i++) m = fmaxf(m, wv[i]);
    float e[16], s = 0.f;
    #pragma unroll
    for (int i = 0; i < 16; i++) { e[i] = __expf(wv[i] - m); s += e[i]; }
    float inv = 1.0f / s;

    float k0 = 0.f, k1 = 0.f, k2 = 0.f, k3 = 0.f;
    #pragma unroll
    for (int i = 0; i < 16; i++) {
        float p = e[i] * inv;
        k0 = fmaf(p, c_gate[i][0], k0);
        k1 = fmaf(p, c_gate[i][1], k1);
        k2 = fmaf(p, c_gate[i][2], k2);
        k3 = fmaf(p, c_gate[i][3], k3);
    }

    unsigned int ia = (unsigned int)load_index(a_idx, j, a64);
    unsigned int ib = (unsigned int)load_index(b_idx, j, b64);

    __half2 h01 = __floats2half2_rn(k0, k1);
    __half2 h23 = __floats2half2_rn(k2, k3);
    uint2 k8;
    k8.x = *reinterpret_cast<unsigned int*>(&h01);
    k8.y = *reinterpret_cast<unsigned int*>(&h23);
    g_k8[j] = k8;
    g_idx_pack[j] = ia | (ib << 16);
}

// Evaluate 2 rows (one half2 lane pair) of one j.
__device__ __forceinline__ void eval_rowpair(uint32_t a_h2, uint32_t b_h2,
                                             float2 k01, float2 k23,
                                             float& v_lo, float& v_hi)
{
    float2 a = __half22float2(*reinterpret_cast<__half2*>(&a_h2));
    float2 b = __half22float2(*reinterpret_cast<__half2*>(&b_h2));
    v_lo = fmaf(a.x, fmaf(k23.y, b.x, k01.y), fmaf(k23.x, b.x, k01.x));
    v_hi = fmaf(a.y, fmaf(k23.y, b.y, k01.y), fmaf(k23.x, b.y, k01.x));
}

// Persistent kernel. smem: one 128KB quad-row slot (uint2 = 4 interleaved halfs)
// + 64KB packed indices. Phases per quad: stage -> sync -> compute -> sync.
// Reads hit DRAM in stage phases, writes drain in compute phases: DRAM busy in both.
__global__ void __launch_bounds__(THREADS, 1)
logic_main_kernel(const float* __restrict__ x, float* __restrict__ out, int nsm)
{
    extern __shared__ __align__(16) unsigned char smem_raw[];
    uint2*    xs4   = reinterpret_cast<uint2*>(smem_raw);                       // 128KB
    uint32_t* s_idx = reinterpret_cast<uint32_t*>(smem_raw + IN_DIM * sizeof(uint2)); // 64KB

    const int c   = blockIdx.x;
    const int tid = threadIdx.x;

    // Load packed indices into smem once (coalesced uint4).
    {
        const uint4* __restrict__ src = reinterpret_cast<const uint4*>(g_idx_pack);
        uint4* __restrict__ dst = reinterpret_cast<uint4*>(s_idx);
        #pragma unroll
        for (int i = 0; i < (OUT_DIM / 4) / THREADS; i++)
            dst[tid + i * THREADS] = __ldg(&src[tid + i * THREADS]);
    }

    for (int q = c; q < QUADS; q += nsm) {
        const float* __restrict__ r0 = x + (size_t)(4 * q) * IN_DIM;

        // ---- stage: 4 fp32 rows -> interleaved half quad ----
        #pragma unroll
        for (int it = 0; it < 4; it++) {
            int k = (tid + it * THREADS) * 4;
            float4 v0 = __ldcs(reinterpret_cast<const float4*>(r0 + k));
            float4 v1 = __ldcs(reinterpret_cast<const float4*>(r0 + IN_DIM + k));
            float4 v2 = __ldcs(reinterpret_cast<const float4*>(r0 + 2 * IN_DIM + k));
            float4 v3 = __ldcs(reinterpret_cast<const float4*>(r0 + 3 * IN_DIM + k));

            __half2 p01[4], p23[4];
            p01[0] = __floats2half2_rn(v0.x, v1.x); p23[0] = __floats2half2_rn(v2.x, v3.x);
            p01[1] = __floats2half2_rn(v0.y, v1.y); p23[1] = __floats2half2_rn(v2.y, v3.y);
            p01[2] = __floats2half2_rn(v0.z, v1.z); p23[2] = __floats2half2_rn(v2.z, v3.z);
            p01[3] = __floats2half2_rn(v0.w, v1.w); p23[3] = __floats2half2_rn(v2.w, v3.w);

            uint4 s0, s1;  // xs4[k..k+1], xs4[k+2..k+3]
            s0.x = *reinterpret_cast<unsigned int*>(&p01[0]);
            s0.y = *reinterpret_cast<unsigned int*>(&p23[0]);
            s0.z = *reinterpret_cast<unsigned int*>(&p01[1]);
            s0.w = *reinterpret_cast<unsigned int*>(&p23[1]);
            s1.x = *reinterpret_cast<unsigned int*>(&p01[2]);
            s1.y = *reinterpret_cast<unsigned int*>(&p23[2]);
            s1.z = *reinterpret_cast<unsigned int*>(&p01[3]);
            s1.w = *reinterpret_cast<unsigned int*>(&p23[3]);
            *reinterpret_cast<uint4*>(&xs4[k])     = s0;
            *reinterpret_cast<uint4*>(&xs4[k + 2]) = s1;
        }
        __syncthreads();

        // ---- compute: 4 rows from the interleaved slot ----
        float* __restrict__ ob = out + (size_t)(4 * q) * OUT_DIM;

        #pragma unroll
        for (int g = 0; g < NGROUP; g++) {
            const int j0 = g * (OUT_DIM / NGROUP) + tid * 4;
            uint4 I   = *reinterpret_cast<const uint4*>(&s_idx[j0]);
            uint4 K01 = __ldg(reinterpret_cast<const uint4*>(&g_k8[j0]));     // j0,j0+1
            uint4 K23 = __ldg(reinterpret_cast<const uint4*>(&g_k8[j0 + 2])); // j0+2,j0+3

            // gathers: one LDS.64 serves all 4 rows
            uint2 av0 = xs4[I.x & 0xFFFFu], bv0 = xs4[I.x >> 16];
            uint2 av1 = xs4[I.y & 0xFFFFu], bv1 = xs4[I.y >> 16];
            uint2 av2 = xs4[I.z & 0xFFFFu], bv2 = xs4[I.z >> 16];
            uint2 av3 = xs4[I.w & 0xFFFFu], bv3 = xs4[I.w >> 16];

            float2 ka01 = __half22float2(*reinterpret_cast<__half2*>(&K01.x));
            float2 ka23 = __half22float2(*reinterpret_cast<__half2*>(&K01.y));
            float2 kb01 = __half22float2(*reinterpret_cast<__half2*>(&K01.z));
            float2 kb23 = __half22float2(*reinterpret_cast<__half2*>(&K01.w));
            float2 kc01 = __half22float2(*reinterpret_cast<__half2*>(&K23.x));
            float2 kc23 = __half22float2(*reinterpret_cast<__half2*>(&K23.y));
            float2 kd01 = __half22float2(*reinterpret_cast<__half2*>(&K23.z));
            float2 kd23 = __half22float2(*reinterpret_cast<__half2*>(&K23.w));

            // rows 0,1 (low half2 of each gather)
            float4 vr0, vr1;
            eval_rowpair(av0.x, bv0.x, ka01, ka23, vr0.x, vr1.x);
            eval_rowpair(av1.x, bv1.x, kb01, kb23, vr0.y, vr1.y);
            eval_rowpair(av2.x, bv2.x, kc01, kc23, vr0.z, vr1.z);
            eval_rowpair(av3.x, bv3.x, kd01, kd23, vr0.w, vr1.w);
            __stcs(reinterpret_cast<float4*>(ob + j0), vr0);
            __stcs(reinterpret_cast<float4*>(ob + OUT_DIM + j0), vr1);

            // rows 2,3 (high half2)
            float4 vr2, vr3;
            eval_rowpair(av0.y, bv0.y, ka01, ka23, vr2.x, vr3.x);
            eval_rowpair(av1.y, bv1.y, kb01, kb23, vr2.y, vr3.y);
            eval_rowpair(av2.y, bv2.y, kc01, kc23, vr2.z, vr3.z);
            eval_rowpair(av3.y, bv3.y, kd01, kd23, vr2.w, vr3.w);
            __stcs(reinterpret_cast<float4*>(ob + 2 * OUT_DIM + j0), vr2);
            __stcs(reinterpret_cast<float4*>(ob + 3 * OUT_DIM + j0), vr3);
        }
        __syncthreads();   // protect slot before next stage
    }
}

extern "C" void kernel_launch(void* const* d_in, const int* in_sizes, int n_in,
                              void* d_out, int out_size)
{
    const float* x  = (const float*)d_in[0];
    const float* w  = (const float*)d_in[1];
    const void*  ai = d_in[2];
    const void*  bi = d_in[3];
    float* out = (float*)d_out;
    (void)in_sizes; (void)n_in; (void)out_size;

    int nsm = 148;
    cudaDeviceGetAttribute(&nsm, cudaDevAttrMultiProcessorCount, 0);

    const int smem_bytes = IN_DIM * sizeof(uint2) + OUT_DIM * sizeof(uint32_t); // 192KB
    cudaFuncSetAttribute(logic_main_kernel,
                         cudaFuncAttributeMaxDynamicSharedMemorySize, smem_bytes);

    prep_kernel<<<(OUT_DIM + 255) / 256, 256>>>(w, ai, bi);
    logic_main_kernel<<<nsm, THREADS, smem_bytes>>>(x, out, nsm);
}

// round 7
// speedup vs baseline: 1.4439x; 1.0539x over previous
#include <cuda_runtime.h>
#include <cuda_fp16.h>
#include <stdint.h>

#define BATCH   4096
#define IN_DIM  16384
#define OUT_DIM 16384
#define THREADS 1024
#define QUADS   (BATCH / 4)               // 1024
#define JPT     (OUT_DIM / THREADS)       // 16 j per thread
#define NGROUP  (JPT / 4)                 // 4 groups of 4 consecutive j

// Per-j k coefficients, 8B: x = half2(k0,k1), y = half2(k2,k3)
__device__ uint2    g_k8[OUT_DIM];
// Per-j packed indices: a | (b<<16)
__device__ uint32_t g_idx_pack[OUT_DIM];

__constant__ float c_gate[16][4] = {
    {0.f, 0.f, 0.f, 0.f}, {0.f, 0.f, 0.f, 1.f}, {0.f, 1.f, 0.f,-1.f}, {0.f, 1.f, 0.f, 0.f},
    {0.f, 0.f, 1.f,-1.f}, {0.f, 0.f, 1.f, 0.f}, {0.f, 1.f, 1.f,-2.f}, {0.f, 1.f, 1.f,-1.f},
    {1.f,-1.f,-1.f, 1.f}, {1.f,-1.f,-1.f, 2.f}, {1.f, 0.f,-1.f, 0.f}, {1.f, 0.f,-1.f, 1.f},
    {1.f,-1.f, 0.f, 0.f}, {1.f,-1.f, 0.f, 1.f}, {1.f, 0.f, 0.f,-1.f}, {1.f, 0.f, 0.f, 0.f}
};

// int64-vs-int32 buffer detection (R1 fix).
__device__ __forceinline__ bool idx_is_int64(const int* p) {
    bool odd_all_zero = true;
    #pragma unroll
    for (int i = 1; i < 64; i += 2) odd_all_zero &= (p[i] == 0);
    return odd_all_zero;
}
__device__ __forceinline__ int load_index(const void* base, int j, bool is64) {
    if (is64) return (int)((const long long*)base)[j];
    return ((const int*)base)[j];
}

__global__ void prep_kernel(const float* __restrict__ w,
                            const void* __restrict__ a_idx,
                            const void* __restrict__ b_idx)
{
    int j = blockIdx.x * blockDim.x + threadIdx.x;
    if (j >= OUT_DIM) return;

    const bool a64 = idx_is_int64((const int*)a_idx);
    const bool b64 = idx_is_int64((const int*)b_idx);

    float wv[16];
    const float4* w4 = reinterpret_cast<const float4*>(w + (size_t)j * 16);
    #pragma unroll
    for (int q = 0; q < 4; q++) {
        float4 v = __ldg(&w4[q]);
        wv[q*4+0] = v.x; wv[q*4+1] = v.y; wv[q*4+2] = v.z; wv[q*4+3] = v.w;
    }
    float m = wv[0];
    #pragma unroll
    for (int i = 1; i < 16; i++) m = fmaxf(m, wv[i]);
    float e[16], s = 0.f;
    #pragma unroll
    for (int i = 0; i < 16; i++) { e[i] = __expf(wv[i] - m); s += e[i]; }
    float inv = 1.0f / s;

    float k0 = 0.f, k1 = 0.f, k2 = 0.f, k3 = 0.f;
    #pragma unroll
    for (int i = 0; i < 16; i++) {
        float p = e[i] * inv;
        k0 = fmaf(p, c_gate[i][0], k0);
        k1 = fmaf(p, c_gate[i][1], k1);
        k2 = fmaf(p, c_gate[i][2], k2);
        k3 = fmaf(p, c_gate[i][3], k3);
    }

    unsigned int ia = (unsigned int)load_index(a_idx, j, a64);
    unsigned int ib = (unsigned int)load_index(b_idx, j, b64);

    __half2 h01 = __floats2half2_rn(k0, k1);
    __half2 h23 = __floats2half2_rn(k2, k3);
    uint2 k8;
    k8.x = *reinterpret_cast<unsigned int*>(&h01);
    k8.y = *reinterpret_cast<unsigned int*>(&h23);
    g_k8[j] = k8;
    g_idx_pack[j] = ia | (ib << 16);
}

__device__ __forceinline__ void prefetch_l2(const void* p) {
    asm volatile("prefetch.global.L2 [%0];" :: "l"(p));
}

// Evaluate 2 rows (one half2 lane pair) of one j.
__device__ __forceinline__ void eval_rowpair(uint32_t a_h2, uint32_t b_h2,
                                             float2 k01, float2 k23,
                                             float& v_lo, float& v_hi)
{
    float2 a = __half22float2(*reinterpret_cast<__half2*>(&a_h2));
    float2 b = __half22float2(*reinterpret_cast<__half2*>(&b_h2));
    v_lo = fmaf(a.x, fmaf(k23.y, b.x, k01.y), fmaf(k23.x, b.x, k01.x));
    v_hi = fmaf(a.y, fmaf(k23.y, b.y, k01.y), fmaf(k23.x, b.y, k01.x));
}

// Persistent kernel. smem: one 128KB quad-row slot (uint2 = 4 interleaved halfs)
// + 64KB packed indices. Per quad: stage (L2-hit LDG.128 -> half -> STS)
// -> sync -> compute (gathers + STG, plus L2 prefetch of NEXT quad) -> sync.
// The prefetch moves DRAM reads into the compute window so DRAM streams
// reads+writes continuously instead of bursting per phase.
__global__ void __launch_bounds__(THREADS, 1)
logic_main_kernel(const float* __restrict__ x, float* __restrict__ out, int nsm)
{
    extern __shared__ __align__(16) unsigned char smem_raw[];
    uint2*    xs4   = reinterpret_cast<uint2*>(smem_raw);                       // 128KB
    uint32_t* s_idx = reinterpret_cast<uint32_t*>(smem_raw + IN_DIM * sizeof(uint2)); // 64KB

    const int c   = blockIdx.x;
    const int tid = threadIdx.x;

    // Load packed indices into smem once (coalesced uint4).
    {
        const uint4* __restrict__ src = reinterpret_cast<const uint4*>(g_idx_pack);
        uint4* __restrict__ dst = reinterpret_cast<uint4*>(s_idx);
        #pragma unroll
        for (int i = 0; i < (OUT_DIM / 4) / THREADS; i++)
            dst[tid + i * THREADS] = __ldg(&src[tid + i * THREADS]);
    }

    // Prefetch the first quad into L2 while the idx load settles.
    {
        const char* base = reinterpret_cast<const char*>(x + (size_t)(4 * c) * IN_DIM);
        prefetch_l2(base + (size_t)tid * 128);
        prefetch_l2(base + (size_t)(tid + THREADS) * 128);
    }

    for (int q = c; q < QUADS; q += nsm) {
        const float* __restrict__ r0 = x + (size_t)(4 * q) * IN_DIM;

        // ---- stage: 4 fp32 rows (L2-resident via prefetch) -> interleaved half quad ----
        #pragma unroll
        for (int it = 0; it < 4; it++) {
            int k = (tid + it * THREADS) * 4;
            float4 v0 = __ldcg(reinterpret_cast<const float4*>(r0 + k));
            float4 v1 = __ldcg(reinterpret_cast<const float4*>(r0 + IN_DIM + k));
            float4 v2 = __ldcg(reinterpret_cast<const float4*>(r0 + 2 * IN_DIM + k));
            float4 v3 = __ldcg(reinterpret_cast<const float4*>(r0 + 3 * IN_DIM + k));

            __half2 p01[4], p23[4];
            p01[0] = __floats2half2_rn(v0.x, v1.x); p23[0] = __floats2half2_rn(v2.x, v3.x);
            p01[1] = __floats2half2_rn(v0.y, v1.y); p23[1] = __floats2half2_rn(v2.y, v3.y);
            p01[2] = __floats2half2_rn(v0.z, v1.z); p23[2] = __floats2half2_rn(v2.z, v3.z);
            p01[3] = __floats2half2_rn(v0.w, v1.w); p23[3] = __floats2half2_rn(v2.w, v3.w);

            uint4 s0, s1;  // xs4[k..k+1], xs4[k+2..k+3]
            s0.x = *reinterpret_cast<unsigned int*>(&p01[0]);
            s0.y = *reinterpret_cast<unsigned int*>(&p23[0]);
            s0.z = *reinterpret_cast<unsigned int*>(&p01[1]);
            s0.w = *reinterpret_cast<unsigned int*>(&p23[1]);
            s1.x = *reinterpret_cast<unsigned int*>(&p01[2]);
            s1.y = *reinterpret_cast<unsigned int*>(&p23[2]);
            s1.z = *reinterpret_cast<unsigned int*>(&p01[3]);
            s1.w = *reinterpret_cast<unsigned int*>(&p23[3]);
            *reinterpret_cast<uint4*>(&xs4[k])     = s0;
            *reinterpret_cast<uint4*>(&xs4[k + 2]) = s1;
        }
        __syncthreads();

        // ---- prefetch NEXT quad's 256KB into L2 (reads overlap this compute) ----
        const int qn = q + nsm;
        if (qn < QUADS) {
            const char* nb = reinterpret_cast<const char*>(x + (size_t)(4 * qn) * IN_DIM);
            prefetch_l2(nb + (size_t)tid * 128);
            prefetch_l2(nb + (size_t)(tid + THREADS) * 128);
        }

        // ---- compute: 4 rows from the interleaved slot ----
        float* __restrict__ ob = out + (size_t)(4 * q) * OUT_DIM;

        #pragma unroll
        for (int g = 0; g < NGROUP; g++) {
            const int j0 = g * (OUT_DIM / NGROUP) + tid * 4;
            uint4 I   = *reinterpret_cast<const uint4*>(&s_idx[j0]);
            uint4 K01 = __ldg(reinterpret_cast<const uint4*>(&g_k8[j0]));     // j0,j0+1
            uint4 K23 = __ldg(reinterpret_cast<const uint4*>(&g_k8[j0 + 2])); // j0+2,j0+3

            // gathers: one LDS.64 serves all 4 rows
            uint2 av0 = xs4[I.x & 0xFFFFu], bv0 = xs4[I.x >> 16];
            uint2 av1 = xs4[I.y & 0xFFFFu], bv1 = xs4[I.y >> 16];
            uint2 av2 = xs4[I.z & 0xFFFFu], bv2 = xs4[I.z >> 16];
            uint2 av3 = xs4[I.w & 0xFFFFu], bv3 = xs4[I.w >> 16];

            float2 ka01 = __half22float2(*reinterpret_cast<__half2*>(&K01.x));
            float2 ka23 = __half22float2(*reinterpret_cast<__half2*>(&K01.y));
            float2 kb01 = __half22float2(*reinterpret_cast<__half2*>(&K01.z));
            float2 kb23 = __half22float2(*reinterpret_cast<__half2*>(&K01.w));
            float2 kc01 = __half22float2(*reinterpret_cast<__half2*>(&K23.x));
            float2 kc23 = __half22float2(*reinterpret_cast<__half2*>(&K23.y));
            float2 kd01 = __half22float2(*reinterpret_cast<__half2*>(&K23.z));
            float2 kd23 = __half22float2(*reinterpret_cast<__half2*>(&K23.w));

            // rows 0,1 (low half2 of each gather)
            float4 vr0, vr1;
            eval_rowpair(av0.x, bv0.x, ka01, ka23, vr0.x, vr1.x);
            eval_rowpair(av1.x, bv1.x, kb01, kb23, vr0.y, vr1.y);
            eval_rowpair(av2.x, bv2.x, kc01, kc23, vr0.z, vr1.z);
            eval_rowpair(av3.x, bv3.x, kd01, kd23, vr0.w, vr1.w);
            __stcs(reinterpret_cast<float4*>(ob + j0), vr0);
            __stcs(reinterpret_cast<float4*>(ob + OUT_DIM + j0), vr1);

            // rows 2,3 (high half2)
            float4 vr2, vr3;
            eval_rowpair(av0.y, bv0.y, ka01, ka23, vr2.x, vr3.x);
            eval_rowpair(av1.y, bv1.y, kb01, kb23, vr2.y, vr3.y);
            eval_rowpair(av2.y, bv2.y, kc01, kc23, vr2.z, vr3.z);
            eval_rowpair(av3.y, bv3.y, kd01, kd23, vr2.w, vr3.w);
            __stcs(reinterpret_cast<float4*>(ob + 2 * OUT_DIM + j0), vr2);
            __stcs(reinterpret_cast<float4*>(ob + 3 * OUT_DIM + j0), vr3);
        }
        __syncthreads();   // protect slot before next stage
    }
}

extern "C" void kernel_launch(void* const* d_in, const int* in_sizes, int n_in,
                              void* d_out, int out_size)
{
    const float* x  = (const float*)d_in[0];
    const float* w  = (const float*)d_in[1];
    const void*  ai = d_in[2];
    const void*  bi = d_in[3];
    float* out = (float*)d_out;
    (void)in_sizes; (void)n_in; (void)out_size;

    int nsm = 148;
    cudaDeviceGetAttribute(&nsm, cudaDevAttrMultiProcessorCount, 0);

    const int smem_bytes = IN_DIM * sizeof(uint2) + OUT_DIM * sizeof(uint32_t); // 192KB
    cudaFuncSetAttribute(logic_main_kernel,
                         cudaFuncAttributeMaxDynamicSharedMemorySize, smem_bytes);

    prep_kernel<<<(OUT_DIM + 255) / 256, 256>>>(w, ai, bi);
    logic_main_kernel<<<nsm, THREADS, smem_bytes>>>(x, out, nsm);
}

// round 8
// speedup vs baseline: 1.4785x; 1.0240x over previous
#include <cuda_runtime.h>
#include <cuda_fp16.h>
#include <stdint.h>

#define BATCH   4096
#define IN_DIM  16384
#define OUT_DIM 16384
#define THREADS 512
#define PAIRS   (BATCH / 2)               // 2048
#define JPT     (OUT_DIM / THREADS)       // 32 j per thread
#define NGROUP  (JPT / 4)                 // 8 groups of 4 consecutive j

// Per-j k coefficients, 8B: x = half2(k0,k1), y = half2(k2,k3)
__device__ uint2    g_k8[OUT_DIM];
// Per-j packed indices: a | (b<<16)
__device__ uint32_t g_idx_pack[OUT_DIM];

__constant__ float c_gate[16][4] = {
    {0.f, 0.f, 0.f, 0.f}, {0.f, 0.f, 0.f, 1.f}, {0.f, 1.f, 0.f,-1.f}, {0.f, 1.f, 0.f, 0.f},
    {0.f, 0.f, 1.f,-1.f}, {0.f, 0.f, 1.f, 0.f}, {0.f, 1.f, 1.f,-2.f}, {0.f, 1.f, 1.f,-1.f},
    {1.f,-1.f,-1.f, 1.f}, {1.f,-1.f,-1.f, 2.f}, {1.f, 0.f,-1.f, 0.f}, {1.f, 0.f,-1.f, 1.f},
    {1.f,-1.f, 0.f, 0.f}, {1.f,-1.f, 0.f, 1.f}, {1.f, 0.f, 0.f,-1.f}, {1.f, 0.f, 0.f, 0.f}
};

// int64-vs-int32 buffer detection (R1 fix).
__device__ __forceinline__ bool idx_is_int64(const int* p) {
    bool odd_all_zero = true;
    #pragma unroll
    for (int i = 1; i < 64; i += 2) odd_all_zero &= (p[i] == 0);
    return odd_all_zero;
}
__device__ __forceinline__ int load_index(const void* base, int j, bool is64) {
    if (is64) return (int)((const long long*)base)[j];
    return ((const int*)base)[j];
}

__global__ void prep_kernel(const float* __restrict__ w,
                            const void* __restrict__ a_idx,
                            const void* __restrict__ b_idx)
{
    int j = blockIdx.x * blockDim.x + threadIdx.x;
    if (j >= OUT_DIM) return;

    const bool a64 = idx_is_int64((const int*)a_idx);
    const bool b64 = idx_is_int64((const int*)b_idx);

    float wv[16];
    const float4* w4 = reinterpret_cast<const float4*>(w + (size_t)j * 16);
    #pragma unroll
    for (int q = 0; q < 4; q++) {
        float4 v = __ldg(&w4[q]);
        wv[q*4+0] = v.x; wv[q*4+1] = v.y; wv[q*4+2] = v.z; wv[q*4+3] = v.w;
    }
    float m = wv[0];
    #pragma unroll
    for (int i = 1; i < 16; i++) m = fmaxf(m, wv[i]);
    float e[16], s = 0.f;
    #pragma unroll
    for (int i = 0; i < 16; i++) { e[i] = __expf(wv[i] - m); s += e[i]; }
    float inv = 1.0f / s;

    float k0 = 0.f, k1 = 0.f, k2 = 0.f, k3 = 0.f;
    #pragma unroll
    for (int i = 0; i < 16; i++) {
        float p = e[i] * inv;
        k0 = fmaf(p, c_gate[i][0], k0);
        k1 = fmaf(p, c_gate[i][1], k1);
        k2 = fmaf(p, c_gate[i][2], k2);
        k3 = fmaf(p, c_gate[i][3], k3);
    }

    unsigned int ia = (unsigned int)load_index(a_idx, j, a64);
    unsigned int ib = (unsigned int)load_index(b_idx, j, b64);

    __half2 h01 = __floats2half2_rn(k0, k1);
    __half2 h23 = __floats2half2_rn(k2, k3);
    uint2 k8;
    k8.x = *reinterpret_cast<unsigned int*>(&h01);
    k8.y = *reinterpret_cast<unsigned int*>(&h23);
    g_k8[j] = k8;
    g_idx_pack[j] = ia | (ib << 16);
}

__device__ __forceinline__ void prefetch_l2(const void* p) {
    asm volatile("prefetch.global.L2 [%0];" :: "l"(p));
}

// Evaluate one j for both rows of the pair.
__device__ __forceinline__ void eval2(uint32_t idxp, uint32_t k01u, uint32_t k23u,
                                      const __half2* __restrict__ xs,
                                      float& ve, float& vo)
{
    float2 k01 = __half22float2(*reinterpret_cast<__half2*>(&k01u));  // k0,k1
    float2 k23 = __half22float2(*reinterpret_cast<__half2*>(&k23u));  // k2,k3
    float2 a = __half22float2(xs[idxp & 0xFFFFu]);
    float2 b = __half22float2(xs[idxp >> 16]);
    ve = fmaf(a.x, fmaf(k23.y, b.x, k01.y), fmaf(k23.x, b.x, k01.x));
    vo = fmaf(a.y, fmaf(k23.y, b.y, k01.y), fmaf(k23.x, b.y, k01.x));
}

// Persistent kernel, 2 CTAs per SM (512 threads each, 64KB smem each).
// Each CTA: pair-interleaved half2 row slot; metadata (k8 + packed idx)
// streamed from L2/L1. Independent CTAs overlap stage/compute phases on
// the SM, removing barrier-exposed idle time.
__global__ void __launch_bounds__(THREADS, 2)
logic_main_kernel(const float* __restrict__ x, float* __restrict__ out, int ncta)
{
    extern __shared__ __align__(16) unsigned char smem_raw[];
    __half2* xs = reinterpret_cast<__half2*>(smem_raw);   // 64KB: {row even, row odd} per col

    const int c   = blockIdx.x;
    const int tid = threadIdx.x;

    // Prefetch first pair (128KB = 1024 lines; 512 threads x 2).
    {
        const char* base = reinterpret_cast<const char*>(x + (size_t)(2 * c) * IN_DIM);
        prefetch_l2(base + (size_t)tid * 128);
        prefetch_l2(base + (size_t)(tid + THREADS) * 128);
    }

    for (int p = c; p < PAIRS; p += ncta) {
        const float* __restrict__ r0 = x + (size_t)(2 * p) * IN_DIM;

        // ---- stage: 2 fp32 rows (L2-resident via prefetch) -> interleaved half2 ----
        #pragma unroll
        for (int it = 0; it < 8; it++) {
            int k = (tid + it * THREADS) * 4;
            float4 e = __ldcg(reinterpret_cast<const float4*>(r0 + k));
            float4 o = __ldcg(reinterpret_cast<const float4*>(r0 + IN_DIM + k));
            __half2 h0 = __floats2half2_rn(e.x, o.x);
            __half2 h1 = __floats2half2_rn(e.y, o.y);
            __half2 h2 = __floats2half2_rn(e.z, o.z);
            __half2 h3 = __floats2half2_rn(e.w, o.w);
            uint4 pk;
            pk.x = *reinterpret_cast<unsigned int*>(&h0);
            pk.y = *reinterpret_cast<unsigned int*>(&h1);
            pk.z = *reinterpret_cast<unsigned int*>(&h2);
            pk.w = *reinterpret_cast<unsigned int*>(&h3);
            *reinterpret_cast<uint4*>(xs + k) = pk;
        }
        __syncthreads();

        // ---- prefetch NEXT pair's 128KB into L2 (reads overlap this compute) ----
        const int pn = p + ncta;
        if (pn < PAIRS) {
            const char* nb = reinterpret_cast<const char*>(x + (size_t)(2 * pn) * IN_DIM);
            prefetch_l2(nb + (size_t)tid * 128);
            prefetch_l2(nb + (size_t)(tid + THREADS) * 128);
        }

        // ---- compute: both rows from the interleaved slot ----
        float* __restrict__ oe = out + (size_t)(2 * p) * OUT_DIM;
        float* __restrict__ oo = oe + OUT_DIM;

        #pragma unroll
        for (int g = 0; g < NGROUP; g++) {
            const int j0 = g * (OUT_DIM / NGROUP) + tid * 4;
            uint4 I   = __ldg(reinterpret_cast<const uint4*>(&g_idx_pack[j0])); // 4 packed idx
            uint4 K01 = __ldg(reinterpret_cast<const uint4*>(&g_k8[j0]));       // k for j0,j0+1
            uint4 K23 = __ldg(reinterpret_cast<const uint4*>(&g_k8[j0 + 2]));   // k for j0+2,j0+3

            float4 ve, vo;
            eval2(I.x, K01.x, K01.y, xs, ve.x, vo.x);
            eval2(I.y, K01.z, K01.w, xs, ve.y, vo.y);
            eval2(I.z, K23.x, K23.y, xs, ve.z, vo.z);
            eval2(I.w, K23.z, K23.w, xs, ve.w, vo.w);

            __stcs(reinterpret_cast<float4*>(&oe[j0]), ve);
            __stcs(reinterpret_cast<float4*>(&oo[j0]), vo);
        }
        __syncthreads();   // protect slot before next stage
    }
}

extern "C" void kernel_launch(void* const* d_in, const int* in_sizes, int n_in,
                              void* d_out, int out_size)
{
    const float* x  = (const float*)d_in[0];
    const float* w  = (const float*)d_in[1];
    const void*  ai = d_in[2];
    const void*  bi = d_in[3];
    float* out = (float*)d_out;
    (void)in_sizes; (void)n_in; (void)out_size;

    int nsm = 148;
    cudaDeviceGetAttribute(&nsm, cudaDevAttrMultiProcessorCount, 0);
    const int ncta = 2 * nsm;   // 2 CTAs per SM

    const int smem_bytes = IN_DIM * sizeof(__half2);   // 64KB per CTA
    cudaFuncSetAttribute(logic_main_kernel,
                         cudaFuncAttributeMaxDynamicSharedMemorySize, smem_bytes);

    prep_kernel<<<(OUT_DIM + 511) / 512, 512>>>(w, ai, bi);
    logic_main_kernel<<<ncta, THREADS, smem_bytes>>>(x, out, ncta);
}